// round 15
// baseline (speedup 1.0000x reference)
#include <cuda_runtime.h>
#include <math.h>
#include <stdint.h>

// Problem constants
#define B_ 2
#define S_ 2048
#define H_ 2048
#define NH_ 32
#define NKV_ 8
#define DH_ 64
#define NREP_ 4
#define QKVW 3072   // NH*DH + 2*NKV*DH

// Scratch (device globals: no allocation allowed)
__device__ float g_qkv[(size_t)B_ * S_ * QKVW];          // Q | K | V per token (tf32-rounded after RoPE)
__device__ float g_attn[(size_t)B_ * S_ * NH_ * DH_];    // attention output (tf32-rounded)
__device__ float g_xr[(size_t)B_ * S_ * H_];             // X rounded to tf32
__device__ float g_w[(size_t)(QKVW + H_) * H_];          // [Wq|Wk|Wv] packed [2048][3072], then Wo [2048][2048]

// ---------------------------------------------------------------------------
// Helpers
// ---------------------------------------------------------------------------
__device__ __forceinline__ void cp_async16(void* smem, const float* gmem) {
    uint32_t s = (uint32_t)__cvta_generic_to_shared(smem);
    asm volatile("cp.async.cg.shared.global [%0], [%1], 16;\n" :: "r"(s), "l"(gmem));
}
#define CP_COMMIT() asm volatile("cp.async.commit_group;\n" ::: "memory")
#define CP_WAIT(n)  asm volatile("cp.async.wait_group %0;\n" :: "n"(n) : "memory")

__device__ __forceinline__ uint32_t f2tf32(float x) {
    uint32_t r;
    asm("cvt.rna.tf32.f32 %0, %1;" : "=r"(r) : "f"(x));
    return r;
}
__device__ __forceinline__ float roundtf(float x) { return __uint_as_float(f2tf32(x)); }

__device__ __forceinline__ void mma_tf32(float* c, const uint32_t* a, uint32_t b0, uint32_t b1) {
    asm volatile(
        "mma.sync.aligned.m16n8k8.row.col.f32.tf32.tf32.f32 "
        "{%0,%1,%2,%3}, {%4,%5,%6,%7}, {%8,%9}, {%0,%1,%2,%3};"
        : "+f"(c[0]), "+f"(c[1]), "+f"(c[2]), "+f"(c[3])
        : "r"(a[0]), "r"(a[1]), "r"(a[2]), "r"(a[3]), "r"(b0), "r"(b1));
}

// ---------------------------------------------------------------------------
// Prep kernels: all tf32 rounding happens HERE, never in mma inner loops.
// ---------------------------------------------------------------------------
__global__ void round_x(const float4* __restrict__ in, float4* __restrict__ out)
{
    int i = blockIdx.x * blockDim.x + threadIdx.x;
    float4 v = in[i];
    v.x = roundtf(v.x); v.y = roundtf(v.y); v.z = roundtf(v.z); v.w = roundtf(v.w);
    out[i] = v;
}

// Pack + round [Wq|Wk|Wv] row-wise into g_w[0 .. 2048*3072). grid.x = 2048 rows.
__global__ void pack_qkv_w(const float4* __restrict__ Wq, const float4* __restrict__ Wk,
                           const float4* __restrict__ Wv, float4* __restrict__ out)
{
    const int k = blockIdx.x;                      // row 0..2047
    float4* orow = out + (size_t)k * (QKVW / 4);   // 768 float4s
    for (int c = threadIdx.x; c < QKVW / 4; c += blockDim.x) {
        float4 v;
        if (c < 512)       v = Wq[(size_t)k * 512 + c];
        else if (c < 640)  v = Wk[(size_t)k * 128 + (c - 512)];
        else               v = Wv[(size_t)k * 128 + (c - 640)];
        v.x = roundtf(v.x); v.y = roundtf(v.y); v.z = roundtf(v.z); v.w = roundtf(v.w);
        orow[c] = v;
    }
}

// ---------------------------------------------------------------------------
// tf32 tensor-core GEMM: C[M,N] = A[M,K] @ W[K,N]. Inputs PRE-ROUNDED to tf32.
// BM=BN=128, BK=32, 128 threads = 4 warps (64x64 warp tiles, 1.0 LDS/mma),
// 2-stage cp.async double buffer, THREE CTAs/SM (reg cap 170) so that
// barrier-desynchronized CTAs fill each other's dependency bubbles.
// A stride 36, B stride 136 -> all fragment LDS conflict-free.
// ---------------------------------------------------------------------------
#define ASZ (128 * 36)
#define BSTR 136
#define BSZ (32 * BSTR)
#define STGF (ASZ + BSZ)               // floats per stage
#define GEMM_SMEM (2 * STGF * 4)       // 71,680 B -> 3 CTAs/SM

__device__ __forceinline__ void gemm_load_tiles(
    const float* __restrict__ A, const float* __restrict__ W,
    float* stage, int K, int N, int mBase, int nBase, int k0, int tid)
{
    float* as = stage;
    float* bs = stage + ASZ;
#pragma unroll
    for (int i = 0; i < 8; i++) {                    // A tile: 128 x 32
        int idx = tid + i * 128;
        int r = idx >> 3, c4 = (idx & 7) * 4;
        cp_async16(as + r * 36 + c4, A + (size_t)(mBase + r) * K + k0 + c4);
    }
#pragma unroll
    for (int i = 0; i < 8; i++) {                    // B tile: 32 x 128
        int idx = tid + i * 128;
        int r = idx >> 5, n4 = (idx & 31) * 4;
        cp_async16(bs + r * BSTR + n4, W + (size_t)(k0 + r) * N + nBase + n4);
    }
}

__global__ __launch_bounds__(128, 3) void gemm_tf32(
    const float* __restrict__ A, const float* __restrict__ W,
    float* __restrict__ C, int K, int N, int ldc)
{
    extern __shared__ float sm[];

    const int tid = threadIdx.x;
    const int lane = tid & 31;
    const int wid = tid >> 5;
    const int wm = wid & 1;          // 2 warps on M: 64 rows each
    const int wn = wid >> 1;         // 2 warps on N: 64 cols each
    const int gid = lane >> 2;       // 0..7
    const int tig = lane & 3;        // 0..3
    const int mBase = blockIdx.y * 128;
    const int nBase = blockIdx.x * 128;

    float acc[4][8][4];
#pragma unroll
    for (int mt = 0; mt < 4; mt++)
#pragma unroll
        for (int nt = 0; nt < 8; nt++)
#pragma unroll
            for (int i = 0; i < 4; i++) acc[mt][nt][i] = 0.f;

    const int T = K >> 5;

    gemm_load_tiles(A, W, sm, K, N, mBase, nBase, 0, tid);
    CP_COMMIT();

    for (int t = 0; t < T; t++) {
        const int buf = t & 1;
        if (t + 1 < T) {
            gemm_load_tiles(A, W, sm + (buf ^ 1) * STGF, K, N, mBase, nBase, (t + 1) * 32, tid);
            CP_COMMIT();
            CP_WAIT(1);
        } else {
            CP_WAIT(0);
        }
        __syncthreads();

        const uint32_t* as = (const uint32_t*)(sm + buf * STGF);
        const uint32_t* bs = as + ASZ;

#pragma unroll
        for (int ks = 0; ks < 4; ks++) {
            const int kk = ks * 8;
            uint32_t af[4][4];
#pragma unroll
            for (int mt = 0; mt < 4; mt++) {
                const uint32_t* ap = as + (wm * 64 + mt * 16 + gid) * 36 + kk + tig;
                af[mt][0] = ap[0];
                af[mt][1] = ap[8 * 36];
                af[mt][2] = ap[4];
                af[mt][3] = ap[8 * 36 + 4];
            }
#pragma unroll
            for (int nt = 0; nt < 8; nt++) {
                const uint32_t* bp = bs + (kk + tig) * BSTR + wn * 64 + nt * 8 + gid;
                uint32_t b0 = bp[0];
                uint32_t b1 = bp[4 * BSTR];
#pragma unroll
                for (int mt = 0; mt < 4; mt++)
                    mma_tf32(acc[mt][nt], af[mt], b0, b1);
            }
        }
        __syncthreads();
    }

#pragma unroll
    for (int mt = 0; mt < 4; mt++) {
#pragma unroll
        for (int nt = 0; nt < 8; nt++) {
            const int r = mBase + wm * 64 + mt * 16 + gid;
            const int c = nBase + wn * 64 + nt * 8 + 2 * tig;
            float2 v0 = make_float2(acc[mt][nt][0], acc[mt][nt][1]);
            float2 v1 = make_float2(acc[mt][nt][2], acc[mt][nt][3]);
            *(float2*)(C + (size_t)r * ldc + c) = v0;
            *(float2*)(C + (size_t)(r + 8) * ldc + c) = v1;
        }
    }
}

// ---------------------------------------------------------------------------
// RoPE in place on Q (heads 0..31) and K (heads 32..39); outputs tf32-rounded.
// ---------------------------------------------------------------------------
__global__ void rope_kernel(const int* __restrict__ pos_ids)
{
    const int bs = blockIdx.x;
    const float p = (float)pos_ids[bs];
    float* base = g_qkv + (size_t)bs * QKVW;

    const float NEG_L2T_OVER_32 = -0.41524101186092029f;   // -log2(10000)/32

    for (int idx = threadIdx.x; idx < (NH_ + NKV_) * 32; idx += blockDim.x) {
        const int head = idx >> 5;
        const int i = idx & 31;
        const float inv = exp2f((float)i * NEG_L2T_OVER_32);
        const float ang = p * inv;
        float sv, cv;
        sincosf(ang, &sv, &cv);
        float* hp = base + head * DH_;
        const float x1 = hp[i];
        const float x2 = hp[i + 32];
        hp[i]      = roundtf(x1 * cv - x2 * sv);
        hp[i + 32] = roundtf(x2 * cv + x1 * sv);
    }
}

// ---------------------------------------------------------------------------
// Tensor-core flash attention (tf32 mma.sync): grid (S/128, NH, B), 128 thr.
// 4 warps, warp owns 32 query rows. qt REVERSED vs blockIdx.x so the most
// expensive CTAs (qt large, cost ~ 2qt+2 tiles) launch first (LPT packing).
// All operands pre-rounded; inner loops pure LDS+MMA. Numerics identical.
// ---------------------------------------------------------------------------
#define FA_PAD 68
#define FQ (128 * FA_PAD)
#define FK (64 * FA_PAD)
#define FV (64 * FA_PAD)
#define FP (128 * FA_PAD)
#define FA_SMEM ((FQ + FK + FV + FP) * 4)

__global__ __launch_bounds__(128, 2) void flash_attn_tc()
{
    extern __shared__ float smf[];
    float* Qs  = smf;
    float* Ks  = smf + FQ;
    float* Vts = Ks + FK;
    float* Ps  = Vts + FV;

    const int qt = gridDim.x - 1 - blockIdx.x;     // longest CTAs first
    const int h = blockIdx.y, b = blockIdx.z;
    const int kh = h >> 2;
    const int tid  = threadIdx.x;
    const int lane = tid & 31;
    const int w    = tid >> 5;      // 0..3, warp owns rows w*32..w*32+31
    const int gid  = lane >> 2;
    const int tig  = lane & 3;
    const int qBase = qt * 128;

    const float* Qg = g_qkv + (size_t)b * S_ * QKVW + h * 64;
    const float* Kg = g_qkv + (size_t)b * S_ * QKVW + 2048 + kh * 64;
    const float* Vg = g_qkv + (size_t)b * S_ * QKVW + 2560 + kh * 64;

    // Q tile 128x64 -> 2048 float4s / 128 threads = 16 iters
#pragma unroll
    for (int i = 0; i < 16; i++) {
        int idx = tid + i * 128;
        int r = idx >> 4, c4 = (idx & 15) * 4;
        cp_async16(Qs + r * FA_PAD + c4, Qg + (size_t)(qBase + r) * QKVW + c4);
    }
    CP_COMMIT();

    float o[2][8][4];
#pragma unroll
    for (int mt = 0; mt < 2; mt++)
#pragma unroll
        for (int df = 0; df < 8; df++)
#pragma unroll
            for (int i = 0; i < 4; i++) o[mt][df][i] = 0.f;
    float m_run[2][2] = {{-INFINITY, -INFINITY}, {-INFINITY, -INFINITY}};
    float l_run[2][2] = {{0.f, 0.f}, {0.f, 0.f}};

    const int nTiles = 2 * qt + 2;
    const int rowMaxW = qBase + w * 32 + 31;

    for (int jt = 0; jt < nTiles; jt++) {
        __syncthreads();

        // K tile 64x64 -> 1024 float4s / 128 threads = 8 iters
#pragma unroll
        for (int i = 0; i < 8; i++) {
            int idx = tid + i * 128;
            int r = idx >> 4, c4 = (idx & 15) * 4;
            cp_async16(Ks + r * FA_PAD + c4, Kg + (size_t)(jt * 64 + r) * QKVW + c4);
        }
        CP_COMMIT();
        // V tile transposed + tf32-rounded: Vts[d][key]
#pragma unroll
        for (int i = 0; i < 8; i++) {
            int idx = tid + i * 128;
            int r = idx >> 4, d4 = (idx & 15) * 4;
            float4 v = *(const float4*)(Vg + (size_t)(jt * 64 + r) * QKVW + d4);
            Vts[(d4 + 0) * FA_PAD + r] = roundtf(v.x);
            Vts[(d4 + 1) * FA_PAD + r] = roundtf(v.y);
            Vts[(d4 + 2) * FA_PAD + r] = roundtf(v.z);
            Vts[(d4 + 3) * FA_PAD + r] = roundtf(v.w);
        }
        CP_WAIT(0);
        __syncthreads();

        if (jt * 64 <= rowMaxW) {
            // ---- S = Q @ K^T (2 m16 tiles x 64 keys) ----
            float s[2][8][4];
#pragma unroll
            for (int mt = 0; mt < 2; mt++)
#pragma unroll
                for (int nf = 0; nf < 8; nf++)
#pragma unroll
                    for (int i = 0; i < 4; i++) s[mt][nf][i] = 0.f;

            const uint32_t* Qu = (const uint32_t*)Qs;
            const uint32_t* Ku = (const uint32_t*)Ks;
#pragma unroll
            for (int ks = 0; ks < 8; ks++) {
                uint32_t af[2][4];
#pragma unroll
                for (int mt = 0; mt < 2; mt++) {
                    const uint32_t* ap = Qu + (w * 32 + mt * 16 + gid) * FA_PAD + ks * 8 + tig;
                    af[mt][0] = ap[0];
                    af[mt][1] = ap[8 * FA_PAD];
                    af[mt][2] = ap[4];
                    af[mt][3] = ap[8 * FA_PAD + 4];
                }
#pragma unroll
                for (int nf = 0; nf < 8; nf++) {
                    const uint32_t* bp = Ku + (nf * 8 + gid) * FA_PAD + ks * 8 + tig;
                    uint32_t b0 = bp[0];
                    uint32_t b1 = bp[4];
                    mma_tf32(s[0][nf], af[0], b0, b1);
                    mma_tf32(s[1][nf], af[1], b0, b1);
                }
            }

            const int cb = jt * 64;
#pragma unroll
            for (int mt = 0; mt < 2; mt++) {
                const int r0 = qBase + w * 32 + mt * 16 + gid;
                const int r1 = r0 + 8;
                // ---- scale + causal mask ----
#pragma unroll
                for (int nf = 0; nf < 8; nf++) {
                    int c0 = cb + nf * 8 + 2 * tig;
                    s[mt][nf][0] = (c0     > r0) ? -1e30f : s[mt][nf][0] * 0.125f;
                    s[mt][nf][1] = (c0 + 1 > r0) ? -1e30f : s[mt][nf][1] * 0.125f;
                    s[mt][nf][2] = (c0     > r1) ? -1e30f : s[mt][nf][2] * 0.125f;
                    s[mt][nf][3] = (c0 + 1 > r1) ? -1e30f : s[mt][nf][3] * 0.125f;
                }

                // ---- online softmax (quad reductions) ----
                float mx0 = -INFINITY, mx1 = -INFINITY;
#pragma unroll
                for (int nf = 0; nf < 8; nf++) {
                    mx0 = fmaxf(mx0, fmaxf(s[mt][nf][0], s[mt][nf][1]));
                    mx1 = fmaxf(mx1, fmaxf(s[mt][nf][2], s[mt][nf][3]));
                }
#pragma unroll
                for (int off = 1; off < 4; off <<= 1) {
                    mx0 = fmaxf(mx0, __shfl_xor_sync(0xffffffffu, mx0, off));
                    mx1 = fmaxf(mx1, __shfl_xor_sync(0xffffffffu, mx1, off));
                }
                const float mn0 = fmaxf(m_run[mt][0], mx0);
                const float mn1 = fmaxf(m_run[mt][1], mx1);
                const float al0 = expf(m_run[mt][0] - mn0);
                const float al1 = expf(m_run[mt][1] - mn1);
                m_run[mt][0] = mn0; m_run[mt][1] = mn1;

                float rs0 = 0.f, rs1 = 0.f;
#pragma unroll
                for (int nf = 0; nf < 8; nf++) {
                    float p0 = expf(s[mt][nf][0] - mn0);
                    float p1 = expf(s[mt][nf][1] - mn0);
                    float p2 = expf(s[mt][nf][2] - mn1);
                    float p3 = expf(s[mt][nf][3] - mn1);
                    s[mt][nf][0] = p0; s[mt][nf][1] = p1; s[mt][nf][2] = p2; s[mt][nf][3] = p3;
                    rs0 += p0 + p1;
                    rs1 += p2 + p3;
                }
#pragma unroll
                for (int off = 1; off < 4; off <<= 1) {
                    rs0 += __shfl_xor_sync(0xffffffffu, rs0, off);
                    rs1 += __shfl_xor_sync(0xffffffffu, rs1, off);
                }
                l_run[mt][0] = l_run[mt][0] * al0 + rs0;
                l_run[mt][1] = l_run[mt][1] * al1 + rs1;
#pragma unroll
                for (int df = 0; df < 8; df++) {
                    o[mt][df][0] *= al0; o[mt][df][1] *= al0;
                    o[mt][df][2] *= al1; o[mt][df][3] *= al1;
                }

                // ---- write P (tf32-rounded; this warp's rows only) ----
                float* pp0 = Ps + (w * 32 + mt * 16 + gid) * FA_PAD;
                float* pp1 = pp0 + 8 * FA_PAD;
#pragma unroll
                for (int nf = 0; nf < 8; nf++) {
                    *(float2*)(pp0 + nf * 8 + 2 * tig) =
                        make_float2(roundtf(s[mt][nf][0]), roundtf(s[mt][nf][1]));
                    *(float2*)(pp1 + nf * 8 + 2 * tig) =
                        make_float2(roundtf(s[mt][nf][2]), roundtf(s[mt][nf][3]));
                }
            }
            __syncwarp();

            // ---- O += P @ V (raw-bit fragments) ----
            const uint32_t* Pu = (const uint32_t*)Ps;
            const uint32_t* Vu = (const uint32_t*)Vts;
#pragma unroll
            for (int ks = 0; ks < 8; ks++) {
                uint32_t af[2][4];
#pragma unroll
                for (int mt = 0; mt < 2; mt++) {
                    const uint32_t* ap = Pu + (w * 32 + mt * 16 + gid) * FA_PAD + ks * 8 + tig;
                    af[mt][0] = ap[0];
                    af[mt][1] = ap[8 * FA_PAD];
                    af[mt][2] = ap[4];
                    af[mt][3] = ap[8 * FA_PAD + 4];
                }
#pragma unroll
                for (int df = 0; df < 8; df++) {
                    const uint32_t* bp = Vu + (df * 8 + gid) * FA_PAD + ks * 8 + tig;
                    uint32_t b0 = bp[0];
                    uint32_t b1 = bp[4];
                    mma_tf32(o[0][df], af[0], b0, b1);
                    mma_tf32(o[1][df], af[1], b0, b1);
                }
            }
        }
    }

    // Epilogue: normalize, round to tf32 (feeds the Wo GEMM), store.
#pragma unroll
    for (int mt = 0; mt < 2; mt++) {
        const float il0 = 1.0f / l_run[mt][0];
        const float il1 = 1.0f / l_run[mt][1];
        const int r0 = qBase + w * 32 + mt * 16 + gid;
        float* Og0 = g_attn + ((size_t)b * S_ + r0) * (NH_ * DH_) + h * 64;
        float* Og1 = Og0 + (size_t)8 * (NH_ * DH_);
#pragma unroll
        for (int df = 0; df < 8; df++) {
            *(float2*)(Og0 + df * 8 + 2 * tig) =
                make_float2(roundtf(o[mt][df][0] * il0), roundtf(o[mt][df][1] * il0));
            *(float2*)(Og1 + df * 8 + 2 * tig) =
                make_float2(roundtf(o[mt][df][2] * il1), roundtf(o[mt][df][3] * il1));
        }
    }
}

// ---------------------------------------------------------------------------
// Launch
// ---------------------------------------------------------------------------
extern "C" void kernel_launch(void* const* d_in, const int* in_sizes, int n_in,
                              void* d_out, int out_size)
{
    const float* X   = (const float*)d_in[0];
    const int*   pos = (const int*)d_in[1];
    const float* Wq  = (const float*)d_in[2];
    const float* Wk  = (const float*)d_in[3];
    const float* Wv  = (const float*)d_in[4];
    const float* Wo  = (const float*)d_in[5];
    float* out = (float*)d_out;

    float *qkv_p, *attn_p, *xr_p, *w_p;
    cudaGetSymbolAddress((void**)&qkv_p, g_qkv);
    cudaGetSymbolAddress((void**)&attn_p, g_attn);
    cudaGetSymbolAddress((void**)&xr_p, g_xr);
    cudaGetSymbolAddress((void**)&w_p, g_w);

    cudaFuncSetAttribute(gemm_tf32, cudaFuncAttributeMaxDynamicSharedMemorySize, GEMM_SMEM);
    cudaFuncSetAttribute(flash_attn_tc, cudaFuncAttributeMaxDynamicSharedMemorySize, FA_SMEM);

    // Pre-round inputs once (no cvt in mma inner loops)
    round_x<<<(B_ * S_ * H_ / 4) / 256, 256>>>((const float4*)X, (float4*)xr_p);
    pack_qkv_w<<<2048, 256>>>((const float4*)Wq, (const float4*)Wk,
                              (const float4*)Wv, (float4*)w_p);
    round_x<<<(H_ * H_ / 4) / 256, 256>>>((const float4*)Wo,
                                          (float4*)(w_p + (size_t)2048 * QKVW));

    // Fused QKV projection: qkv[4096,3072] = Xr @ [Wq|Wk|Wv]
    gemm_tf32<<<dim3(24, 32), 128, GEMM_SMEM>>>(xr_p, w_p, qkv_p, 2048, QKVW, QKVW);

    // RoPE on Q and K in place (tf32-rounded outputs)
    rope_kernel<<<B_ * S_, 256>>>(pos);

    // Tensor-core flash attention (longest CTAs first)
    flash_attn_tc<<<dim3(S_ / 128, NH_, B_), 128, FA_SMEM>>>();

    // Output projection: out = attn @ Wo
    gemm_tf32<<<dim3(16, 32), 128, GEMM_SMEM>>>(attn_p, w_p + (size_t)2048 * QKVW,
                                                out, 2048, 2048, 2048);
}

// round 16
// speedup vs baseline: 1.5982x; 1.5982x over previous
#include <cuda_runtime.h>
#include <math.h>
#include <stdint.h>

// Problem constants
#define B_ 2
#define S_ 2048
#define H_ 2048
#define NH_ 32
#define NKV_ 8
#define DH_ 64
#define NREP_ 4
#define QKVW 3072   // NH*DH + 2*NKV*DH

// Scratch (device globals: no allocation allowed)
__device__ float g_qkv[(size_t)B_ * S_ * QKVW];          // Q | K | V per token (tf32-rounded after RoPE)
__device__ float g_attn[(size_t)B_ * S_ * NH_ * DH_];    // attention output (tf32-rounded)
__device__ float g_xr[(size_t)B_ * S_ * H_];             // X rounded to tf32
__device__ float g_w[(size_t)(QKVW + H_) * H_];          // [Wq|Wk|Wv] packed [2048][3072], then Wo [2048][2048]

// ---------------------------------------------------------------------------
// Helpers
// ---------------------------------------------------------------------------
__device__ __forceinline__ void cp_async16(void* smem, const float* gmem) {
    uint32_t s = (uint32_t)__cvta_generic_to_shared(smem);
    asm volatile("cp.async.cg.shared.global [%0], [%1], 16;\n" :: "r"(s), "l"(gmem));
}
#define CP_COMMIT() asm volatile("cp.async.commit_group;\n" ::: "memory")
#define CP_WAIT(n)  asm volatile("cp.async.wait_group %0;\n" :: "n"(n) : "memory")

__device__ __forceinline__ uint32_t f2tf32(float x) {
    uint32_t r;
    asm("cvt.rna.tf32.f32 %0, %1;" : "=r"(r) : "f"(x));
    return r;
}
__device__ __forceinline__ float roundtf(float x) { return __uint_as_float(f2tf32(x)); }

__device__ __forceinline__ void mma_tf32(float* c, const uint32_t* a, uint32_t b0, uint32_t b1) {
    asm volatile(
        "mma.sync.aligned.m16n8k8.row.col.f32.tf32.tf32.f32 "
        "{%0,%1,%2,%3}, {%4,%5,%6,%7}, {%8,%9}, {%0,%1,%2,%3};"
        : "+f"(c[0]), "+f"(c[1]), "+f"(c[2]), "+f"(c[3])
        : "r"(a[0]), "r"(a[1]), "r"(a[2]), "r"(a[3]), "r"(b0), "r"(b1));
}

// ---------------------------------------------------------------------------
// Prep kernels: all tf32 rounding happens HERE, never in mma inner loops.
// ---------------------------------------------------------------------------
__global__ void round_x(const float4* __restrict__ in, float4* __restrict__ out)
{
    int i = blockIdx.x * blockDim.x + threadIdx.x;
    float4 v = in[i];
    v.x = roundtf(v.x); v.y = roundtf(v.y); v.z = roundtf(v.z); v.w = roundtf(v.w);
    out[i] = v;
}

// Pack + round [Wq|Wk|Wv] row-wise into g_w[0 .. 2048*3072). grid.x = 2048 rows.
__global__ void pack_qkv_w(const float4* __restrict__ Wq, const float4* __restrict__ Wk,
                           const float4* __restrict__ Wv, float4* __restrict__ out)
{
    const int k = blockIdx.x;                      // row 0..2047
    float4* orow = out + (size_t)k * (QKVW / 4);   // 768 float4s
    for (int c = threadIdx.x; c < QKVW / 4; c += blockDim.x) {
        float4 v;
        if (c < 512)       v = Wq[(size_t)k * 512 + c];
        else if (c < 640)  v = Wk[(size_t)k * 128 + (c - 512)];
        else               v = Wv[(size_t)k * 128 + (c - 640)];
        v.x = roundtf(v.x); v.y = roundtf(v.y); v.z = roundtf(v.z); v.w = roundtf(v.w);
        orow[c] = v;
    }
}

// ---------------------------------------------------------------------------
// tf32 tensor-core GEMM: C[M,N] = A[M,K] @ W[K,N]. Inputs PRE-ROUNDED to tf32.
// BM=BN=128, BK=32. 256 threads = 8 warps, warp tile 64x32 (2Mx4N grid):
// acc = 64 regs/thread -> ~115 regs -> 2 CTAs/SM = 16 warps/SM (4/SMSP),
// filling per-warp LDS->mma dependency bubbles. 2-stage cp.async.
// A stride 36, B stride 136 -> all fragment LDS conflict-free.
// ---------------------------------------------------------------------------
#define ASZ (128 * 36)
#define BSTR 136
#define BSZ (32 * BSTR)
#define STGF (ASZ + BSZ)               // floats per stage
#define GEMM_SMEM (2 * STGF * 4)       // 71,680 B -> 2 CTAs/SM (256 thr)

__device__ __forceinline__ void gemm_load_tiles(
    const float* __restrict__ A, const float* __restrict__ W,
    float* stage, int K, int N, int mBase, int nBase, int k0, int tid)
{
    float* as = stage;
    float* bs = stage + ASZ;
#pragma unroll
    for (int i = 0; i < 4; i++) {                    // A tile: 128 x 32
        int idx = tid + i * 256;
        int r = idx >> 3, c4 = (idx & 7) * 4;
        cp_async16(as + r * 36 + c4, A + (size_t)(mBase + r) * K + k0 + c4);
    }
#pragma unroll
    for (int i = 0; i < 4; i++) {                    // B tile: 32 x 128
        int idx = tid + i * 256;
        int r = idx >> 5, n4 = (idx & 31) * 4;
        cp_async16(bs + r * BSTR + n4, W + (size_t)(k0 + r) * N + nBase + n4);
    }
}

__global__ __launch_bounds__(256, 2) void gemm_tf32(
    const float* __restrict__ A, const float* __restrict__ W,
    float* __restrict__ C, int K, int N, int ldc)
{
    extern __shared__ float sm[];

    const int tid = threadIdx.x;
    const int lane = tid & 31;
    const int wid = tid >> 5;
    const int wm = wid & 1;          // 2 warps on M: 64 rows each
    const int wn = wid >> 1;         // 4 warps on N: 32 cols each
    const int gid = lane >> 2;       // 0..7
    const int tig = lane & 3;        // 0..3
    const int mBase = blockIdx.y * 128;
    const int nBase = blockIdx.x * 128;

    float acc[4][4][4];
#pragma unroll
    for (int mt = 0; mt < 4; mt++)
#pragma unroll
        for (int nt = 0; nt < 4; nt++)
#pragma unroll
            for (int i = 0; i < 4; i++) acc[mt][nt][i] = 0.f;

    const int T = K >> 5;

    gemm_load_tiles(A, W, sm, K, N, mBase, nBase, 0, tid);
    CP_COMMIT();

    for (int t = 0; t < T; t++) {
        const int buf = t & 1;
        if (t + 1 < T) {
            gemm_load_tiles(A, W, sm + (buf ^ 1) * STGF, K, N, mBase, nBase, (t + 1) * 32, tid);
            CP_COMMIT();
            CP_WAIT(1);
        } else {
            CP_WAIT(0);
        }
        __syncthreads();

        const uint32_t* as = (const uint32_t*)(sm + buf * STGF);
        const uint32_t* bs = as + ASZ;

#pragma unroll
        for (int ks = 0; ks < 4; ks++) {
            const int kk = ks * 8;
            uint32_t af[4][4];
#pragma unroll
            for (int mt = 0; mt < 4; mt++) {
                const uint32_t* ap = as + (wm * 64 + mt * 16 + gid) * 36 + kk + tig;
                af[mt][0] = ap[0];
                af[mt][1] = ap[8 * 36];
                af[mt][2] = ap[4];
                af[mt][3] = ap[8 * 36 + 4];
            }
#pragma unroll
            for (int nt = 0; nt < 4; nt++) {
                const uint32_t* bp = bs + (kk + tig) * BSTR + wn * 32 + nt * 8 + gid;
                uint32_t b0 = bp[0];
                uint32_t b1 = bp[4 * BSTR];
#pragma unroll
                for (int mt = 0; mt < 4; mt++)
                    mma_tf32(acc[mt][nt], af[mt], b0, b1);
            }
        }
        __syncthreads();
    }

#pragma unroll
    for (int mt = 0; mt < 4; mt++) {
#pragma unroll
        for (int nt = 0; nt < 4; nt++) {
            const int r = mBase + wm * 64 + mt * 16 + gid;
            const int c = nBase + wn * 32 + nt * 8 + 2 * tig;
            float2 v0 = make_float2(acc[mt][nt][0], acc[mt][nt][1]);
            float2 v1 = make_float2(acc[mt][nt][2], acc[mt][nt][3]);
            *(float2*)(C + (size_t)r * ldc + c) = v0;
            *(float2*)(C + (size_t)(r + 8) * ldc + c) = v1;
        }
    }
}

// ---------------------------------------------------------------------------
// RoPE in place on Q (heads 0..31) and K (heads 32..39); outputs tf32-rounded.
// ---------------------------------------------------------------------------
__global__ void rope_kernel(const int* __restrict__ pos_ids)
{
    const int bs = blockIdx.x;
    const float p = (float)pos_ids[bs];
    float* base = g_qkv + (size_t)bs * QKVW;

    const float NEG_L2T_OVER_32 = -0.41524101186092029f;   // -log2(10000)/32

    for (int idx = threadIdx.x; idx < (NH_ + NKV_) * 32; idx += blockDim.x) {
        const int head = idx >> 5;
        const int i = idx & 31;
        const float inv = exp2f((float)i * NEG_L2T_OVER_32);
        const float ang = p * inv;
        float sv, cv;
        sincosf(ang, &sv, &cv);
        float* hp = base + head * DH_;
        const float x1 = hp[i];
        const float x2 = hp[i + 32];
        hp[i]      = roundtf(x1 * cv - x2 * sv);
        hp[i + 32] = roundtf(x2 * cv + x1 * sv);
    }
}

// ---------------------------------------------------------------------------
// Tensor-core flash attention (tf32 mma.sync): grid (S/128, NH, B), 128 thr.
// 4 warps, warp owns 32 query rows (2 m16 tiles). EXACT R12-passing version.
// ---------------------------------------------------------------------------
#define FA_PAD 68
#define FQ (128 * FA_PAD)
#define FK (64 * FA_PAD)
#define FV (64 * FA_PAD)
#define FP (128 * FA_PAD)
#define FA_SMEM ((FQ + FK + FV + FP) * 4)

__global__ __launch_bounds__(128, 2) void flash_attn_tc()
{
    extern __shared__ float smf[];
    float* Qs  = smf;
    float* Ks  = smf + FQ;
    float* Vts = Ks + FK;
    float* Ps  = Vts + FV;

    const int qt = blockIdx.x, h = blockIdx.y, b = blockIdx.z;
    const int kh = h >> 2;
    const int tid  = threadIdx.x;
    const int lane = tid & 31;
    const int w    = tid >> 5;      // 0..3, warp owns rows w*32..w*32+31
    const int gid  = lane >> 2;
    const int tig  = lane & 3;
    const int qBase = qt * 128;

    const float* Qg = g_qkv + (size_t)b * S_ * QKVW + h * 64;
    const float* Kg = g_qkv + (size_t)b * S_ * QKVW + 2048 + kh * 64;
    const float* Vg = g_qkv + (size_t)b * S_ * QKVW + 2560 + kh * 64;

    // Q tile 128x64 -> 2048 float4s / 128 threads = 16 iters
#pragma unroll
    for (int i = 0; i < 16; i++) {
        int idx = tid + i * 128;
        int r = idx >> 4, c4 = (idx & 15) * 4;
        cp_async16(Qs + r * FA_PAD + c4, Qg + (size_t)(qBase + r) * QKVW + c4);
    }
    CP_COMMIT();

    float o[2][8][4];
#pragma unroll
    for (int mt = 0; mt < 2; mt++)
#pragma unroll
        for (int df = 0; df < 8; df++)
#pragma unroll
            for (int i = 0; i < 4; i++) o[mt][df][i] = 0.f;
    float m_run[2][2] = {{-INFINITY, -INFINITY}, {-INFINITY, -INFINITY}};
    float l_run[2][2] = {{0.f, 0.f}, {0.f, 0.f}};

    const int nTiles = 2 * qt + 2;
    const int rowMaxW = qBase + w * 32 + 31;

    for (int jt = 0; jt < nTiles; jt++) {
        __syncthreads();

        // K tile 64x64 -> 1024 float4s / 128 threads = 8 iters
#pragma unroll
        for (int i = 0; i < 8; i++) {
            int idx = tid + i * 128;
            int r = idx >> 4, c4 = (idx & 15) * 4;
            cp_async16(Ks + r * FA_PAD + c4, Kg + (size_t)(jt * 64 + r) * QKVW + c4);
        }
        CP_COMMIT();
        // V tile transposed + tf32-rounded: Vts[d][key]
#pragma unroll
        for (int i = 0; i < 8; i++) {
            int idx = tid + i * 128;
            int r = idx >> 4, d4 = (idx & 15) * 4;
            float4 v = *(const float4*)(Vg + (size_t)(jt * 64 + r) * QKVW + d4);
            Vts[(d4 + 0) * FA_PAD + r] = roundtf(v.x);
            Vts[(d4 + 1) * FA_PAD + r] = roundtf(v.y);
            Vts[(d4 + 2) * FA_PAD + r] = roundtf(v.z);
            Vts[(d4 + 3) * FA_PAD + r] = roundtf(v.w);
        }
        CP_WAIT(0);
        __syncthreads();

        if (jt * 64 <= rowMaxW) {
            // ---- S = Q @ K^T (2 m16 tiles x 64 keys) ----
            float s[2][8][4];
#pragma unroll
            for (int mt = 0; mt < 2; mt++)
#pragma unroll
                for (int nf = 0; nf < 8; nf++)
#pragma unroll
                    for (int i = 0; i < 4; i++) s[mt][nf][i] = 0.f;

            const uint32_t* Qu = (const uint32_t*)Qs;
            const uint32_t* Ku = (const uint32_t*)Ks;
#pragma unroll
            for (int ks = 0; ks < 8; ks++) {
                uint32_t af[2][4];
#pragma unroll
                for (int mt = 0; mt < 2; mt++) {
                    const uint32_t* ap = Qu + (w * 32 + mt * 16 + gid) * FA_PAD + ks * 8 + tig;
                    af[mt][0] = ap[0];
                    af[mt][1] = ap[8 * FA_PAD];
                    af[mt][2] = ap[4];
                    af[mt][3] = ap[8 * FA_PAD + 4];
                }
#pragma unroll
                for (int nf = 0; nf < 8; nf++) {
                    const uint32_t* bp = Ku + (nf * 8 + gid) * FA_PAD + ks * 8 + tig;
                    uint32_t b0 = bp[0];
                    uint32_t b1 = bp[4];
                    mma_tf32(s[0][nf], af[0], b0, b1);
                    mma_tf32(s[1][nf], af[1], b0, b1);
                }
            }

            const int cb = jt * 64;
#pragma unroll
            for (int mt = 0; mt < 2; mt++) {
                const int r0 = qBase + w * 32 + mt * 16 + gid;
                const int r1 = r0 + 8;
                // ---- scale + causal mask ----
#pragma unroll
                for (int nf = 0; nf < 8; nf++) {
                    int c0 = cb + nf * 8 + 2 * tig;
                    s[mt][nf][0] = (c0     > r0) ? -1e30f : s[mt][nf][0] * 0.125f;
                    s[mt][nf][1] = (c0 + 1 > r0) ? -1e30f : s[mt][nf][1] * 0.125f;
                    s[mt][nf][2] = (c0     > r1) ? -1e30f : s[mt][nf][2] * 0.125f;
                    s[mt][nf][3] = (c0 + 1 > r1) ? -1e30f : s[mt][nf][3] * 0.125f;
                }

                // ---- online softmax (quad reductions) ----
                float mx0 = -INFINITY, mx1 = -INFINITY;
#pragma unroll
                for (int nf = 0; nf < 8; nf++) {
                    mx0 = fmaxf(mx0, fmaxf(s[mt][nf][0], s[mt][nf][1]));
                    mx1 = fmaxf(mx1, fmaxf(s[mt][nf][2], s[mt][nf][3]));
                }
#pragma unroll
                for (int off = 1; off < 4; off <<= 1) {
                    mx0 = fmaxf(mx0, __shfl_xor_sync(0xffffffffu, mx0, off));
                    mx1 = fmaxf(mx1, __shfl_xor_sync(0xffffffffu, mx1, off));
                }
                const float mn0 = fmaxf(m_run[mt][0], mx0);
                const float mn1 = fmaxf(m_run[mt][1], mx1);
                const float al0 = expf(m_run[mt][0] - mn0);
                const float al1 = expf(m_run[mt][1] - mn1);
                m_run[mt][0] = mn0; m_run[mt][1] = mn1;

                float rs0 = 0.f, rs1 = 0.f;
#pragma unroll
                for (int nf = 0; nf < 8; nf++) {
                    float p0 = expf(s[mt][nf][0] - mn0);
                    float p1 = expf(s[mt][nf][1] - mn0);
                    float p2 = expf(s[mt][nf][2] - mn1);
                    float p3 = expf(s[mt][nf][3] - mn1);
                    s[mt][nf][0] = p0; s[mt][nf][1] = p1; s[mt][nf][2] = p2; s[mt][nf][3] = p3;
                    rs0 += p0 + p1;
                    rs1 += p2 + p3;
                }
#pragma unroll
                for (int off = 1; off < 4; off <<= 1) {
                    rs0 += __shfl_xor_sync(0xffffffffu, rs0, off);
                    rs1 += __shfl_xor_sync(0xffffffffu, rs1, off);
                }
                l_run[mt][0] = l_run[mt][0] * al0 + rs0;
                l_run[mt][1] = l_run[mt][1] * al1 + rs1;
#pragma unroll
                for (int df = 0; df < 8; df++) {
                    o[mt][df][0] *= al0; o[mt][df][1] *= al0;
                    o[mt][df][2] *= al1; o[mt][df][3] *= al1;
                }

                // ---- write P (tf32-rounded; this warp's rows only) ----
                float* pp0 = Ps + (w * 32 + mt * 16 + gid) * FA_PAD;
                float* pp1 = pp0 + 8 * FA_PAD;
#pragma unroll
                for (int nf = 0; nf < 8; nf++) {
                    *(float2*)(pp0 + nf * 8 + 2 * tig) =
                        make_float2(roundtf(s[mt][nf][0]), roundtf(s[mt][nf][1]));
                    *(float2*)(pp1 + nf * 8 + 2 * tig) =
                        make_float2(roundtf(s[mt][nf][2]), roundtf(s[mt][nf][3]));
                }
            }
            __syncwarp();

            // ---- O += P @ V (raw-bit fragments) ----
            const uint32_t* Pu = (const uint32_t*)Ps;
            const uint32_t* Vu = (const uint32_t*)Vts;
#pragma unroll
            for (int ks = 0; ks < 8; ks++) {
                uint32_t af[2][4];
#pragma unroll
                for (int mt = 0; mt < 2; mt++) {
                    const uint32_t* ap = Pu + (w * 32 + mt * 16 + gid) * FA_PAD + ks * 8 + tig;
                    af[mt][0] = ap[0];
                    af[mt][1] = ap[8 * FA_PAD];
                    af[mt][2] = ap[4];
                    af[mt][3] = ap[8 * FA_PAD + 4];
                }
#pragma unroll
                for (int df = 0; df < 8; df++) {
                    const uint32_t* bp = Vu + (df * 8 + gid) * FA_PAD + ks * 8 + tig;
                    uint32_t b0 = bp[0];
                    uint32_t b1 = bp[4];
                    mma_tf32(o[0][df], af[0], b0, b1);
                    mma_tf32(o[1][df], af[1], b0, b1);
                }
            }
        }
    }

    // Epilogue: normalize, round to tf32 (feeds the Wo GEMM), store.
#pragma unroll
    for (int mt = 0; mt < 2; mt++) {
        const float il0 = 1.0f / l_run[mt][0];
        const float il1 = 1.0f / l_run[mt][1];
        const int r0 = qBase + w * 32 + mt * 16 + gid;
        float* Og0 = g_attn + ((size_t)b * S_ + r0) * (NH_ * DH_) + h * 64;
        float* Og1 = Og0 + (size_t)8 * (NH_ * DH_);
#pragma unroll
        for (int df = 0; df < 8; df++) {
            *(float2*)(Og0 + df * 8 + 2 * tig) =
                make_float2(roundtf(o[mt][df][0] * il0), roundtf(o[mt][df][1] * il0));
            *(float2*)(Og1 + df * 8 + 2 * tig) =
                make_float2(roundtf(o[mt][df][2] * il1), roundtf(o[mt][df][3] * il1));
        }
    }
}

// ---------------------------------------------------------------------------
// Launch
// ---------------------------------------------------------------------------
extern "C" void kernel_launch(void* const* d_in, const int* in_sizes, int n_in,
                              void* d_out, int out_size)
{
    const float* X   = (const float*)d_in[0];
    const int*   pos = (const int*)d_in[1];
    const float* Wq  = (const float*)d_in[2];
    const float* Wk  = (const float*)d_in[3];
    const float* Wv  = (const float*)d_in[4];
    const float* Wo  = (const float*)d_in[5];
    float* out = (float*)d_out;

    float *qkv_p, *attn_p, *xr_p, *w_p;
    cudaGetSymbolAddress((void**)&qkv_p, g_qkv);
    cudaGetSymbolAddress((void**)&attn_p, g_attn);
    cudaGetSymbolAddress((void**)&xr_p, g_xr);
    cudaGetSymbolAddress((void**)&w_p, g_w);

    cudaFuncSetAttribute(gemm_tf32, cudaFuncAttributeMaxDynamicSharedMemorySize, GEMM_SMEM);
    cudaFuncSetAttribute(flash_attn_tc, cudaFuncAttributeMaxDynamicSharedMemorySize, FA_SMEM);

    // Pre-round inputs once (no cvt in mma inner loops)
    round_x<<<(B_ * S_ * H_ / 4) / 256, 256>>>((const float4*)X, (float4*)xr_p);
    pack_qkv_w<<<2048, 256>>>((const float4*)Wq, (const float4*)Wk,
                              (const float4*)Wv, (float4*)w_p);
    round_x<<<(H_ * H_ / 4) / 256, 256>>>((const float4*)Wo,
                                          (float4*)(w_p + (size_t)2048 * QKVW));

    // Fused QKV projection: qkv[4096,3072] = Xr @ [Wq|Wk|Wv]
    gemm_tf32<<<dim3(24, 32), 256, GEMM_SMEM>>>(xr_p, w_p, qkv_p, 2048, QKVW, QKVW);

    // RoPE on Q and K in place (tf32-rounded outputs)
    rope_kernel<<<B_ * S_, 256>>>(pos);

    // Tensor-core flash attention (exact R12 version)
    flash_attn_tc<<<dim3(S_ / 128, NH_, B_), 128, FA_SMEM>>>();

    // Output projection: out = attn @ Wo
    gemm_tf32<<<dim3(16, 32), 256, GEMM_SMEM>>>(attn_p, w_p + (size_t)2048 * QKVW,
                                                out, 2048, 2048, 2048);
}